// round 3
// baseline (speedup 1.0000x reference)
#include <cuda_runtime.h>

// AELoss fused single-launch, serial-chain-optimized.
// pred/target (64,4,256,256) fp32, match (64,128,2,2) int32.
// out[0] = 0.25 * sum_b pull_b, out[1] = 0.25 * sum_b push_b
//
// pull_b = sum_{n,c} (tl-br)^2 / 2 / N        (since tl-me = (tl-br)/2)
// push_b = sum_{i!=j} relu(1 - |s_i - s_j|) / (N*(N-1)),  s_i = sum_c (tl+br)/2

#define B_IMGS 64
#define N_KP   128
#define C_CH   4
#define HW     65536   // 256*256
#define W_DIM  256
#define GROUPS 8       // two-level completion tree: 8 groups of 8 blocks

__device__ float g_scratch[2 * B_IMGS];   // [0..63]=pull_b, [64..127]=push_b
__device__ unsigned int g_cnt1[GROUPS];   // level-1 arrival counters (spread addrs)
__device__ unsigned int g_cnt2;           // level-2 counter

__global__ __launch_bounds__(N_KP, 1)
void ae_fused_kernel(const float* __restrict__ pred,
                     const float* __restrict__ target,
                     const int*   __restrict__ match,
                     float*       __restrict__ out) {
    const int b = blockIdx.x;
    const int n = threadIdx.x;

    __shared__ float s_me[N_KP];
    __shared__ float s_red[8];    // 4 warps x 2 values
    __shared__ int   s_last;

    // match[b, n, {tl,br}, {y,x}] -- one int4 per (b,n)
    const int4 m = __ldg(reinterpret_cast<const int4*>(match) + b * N_KP + n);
    const int tl_off = m.x * W_DIM + m.y;
    const int br_off = m.z * W_DIM + m.w;

    const float* __restrict__ p = pred   + (size_t)b * C_CH * HW;
    const float* __restrict__ t = target + (size_t)b * C_CH * HW;

    float pull = 0.0f;
    float s    = 0.0f;
    #pragma unroll
    for (int c = 0; c < C_CH; ++c) {
        const float tl = __ldg(p + c * HW + tl_off);
        const float br = __ldg(t + c * HW + br_off);
        const float d = tl - br;
        pull += 0.5f * d * d;
        s    += 0.5f * (tl + br);
    }
    s_me[n] = s;
    __syncthreads();

    // push: 4 independent accumulators to break the FADD RAW chain
    float p0 = 0.0f, p1 = 0.0f, p2 = 0.0f, p3 = 0.0f;
    const float4* __restrict__ s4 = reinterpret_cast<const float4*>(s_me);
    #pragma unroll
    for (int j = 0; j < N_KP / 4; ++j) {
        const float4 v = s4[j];
        p0 += fmaxf(0.0f, 1.0f - fabsf(s - v.x));
        p1 += fmaxf(0.0f, 1.0f - fabsf(s - v.y));
        p2 += fmaxf(0.0f, 1.0f - fabsf(s - v.z));
        p3 += fmaxf(0.0f, 1.0f - fabsf(s - v.w));
    }
    float push = ((p0 + p1) + (p2 + p3)) - 1.0f;   // remove the j==n term (==1)

    // block reduction of (pull, push)
    #pragma unroll
    for (int off = 16; off > 0; off >>= 1) {
        pull += __shfl_down_sync(0xFFFFFFFFu, pull, off);
        push += __shfl_down_sync(0xFFFFFFFFu, push, off);
    }
    const int warp = n >> 5;
    const int lane = n & 31;
    if (lane == 0) {
        s_red[warp]     = pull;
        s_red[4 + warp] = push;
    }
    __syncthreads();

    if (n == 0) {
        const float pu = s_red[0] + s_red[1] + s_red[2] + s_red[3];
        const float ph = s_red[4] + s_red[5] + s_red[6] + s_red[7];
        __stcg(&g_scratch[b],          pu * (1.0f / (float)N_KP));
        __stcg(&g_scratch[B_IMGS + b], ph * (1.0f / (float)(N_KP * (N_KP - 1))));
        __threadfence();
        // two-level completion tree: 8 atomics per address instead of 64
        int last = 0;
        const unsigned int old1 = atomicAdd(&g_cnt1[b >> 3], 1u);
        if (old1 == 7u) {
            const unsigned int old2 = atomicAdd(&g_cnt2, 1u);
            last = (old2 == (unsigned)(GROUPS - 1)) ? 1 : 0;
        }
        s_last = last;
    }
    __syncthreads();

    // Last block performs the final deterministic reduction.
    if (s_last && warp == 0) {
        __threadfence();  // acquire: order g_scratch reads after the atomics
        float pu = __ldcg(&g_scratch[lane]) + __ldcg(&g_scratch[lane + 32]);
        float ph = __ldcg(&g_scratch[B_IMGS + lane]) + __ldcg(&g_scratch[B_IMGS + lane + 32]);
        #pragma unroll
        for (int off = 16; off > 0; off >>= 1) {
            pu += __shfl_down_sync(0xFFFFFFFFu, pu, off);
            ph += __shfl_down_sync(0xFFFFFFFFu, ph, off);
        }
        if (lane == 0) {
            out[0] = 0.25f * pu;
            out[1] = 0.25f * ph;
            g_cnt2 = 0;                       // reset for next graph replay
        }
        if (lane < GROUPS) g_cnt1[lane] = 0;  // reset level-1 counters
    }
}

extern "C" void kernel_launch(void* const* d_in, const int* in_sizes, int n_in,
                              void* d_out, int out_size) {
    const float* pred   = (const float*)d_in[0];
    const float* target = (const float*)d_in[1];
    const int*   match  = (const int*)d_in[2];
    float* out = (float*)d_out;

    ae_fused_kernel<<<B_IMGS, N_KP>>>(pred, target, match, out);
}

// round 4
// speedup vs baseline: 1.0294x; 1.0294x over previous
#include <cuda_runtime.h>
#include <cooperative_groups.h>
namespace cg = cooperative_groups;

// AELoss: pred/target (64,4,256,256) fp32, match (64,128,2,2) int32.
// out[0] = 0.25 * sum_b pull_b, out[1] = 0.25 * sum_b push_b
//
// pull_b = sum_{n,c} (tl-br)^2 / 2 / N        (tl-me = (tl-br)/2)
// push_b = sum_{i!=j} relu(1 - |s_i - s_j|) / (N*(N-1)),  s_i = sum_c (tl+br)/2
//
// Layout: 2 CTAs per image (cluster), 64 keypoints each.
// Thread n: kp k = n>>1 (local), channel-half h = n&1 -> channels {2h, 2h+1}.
// 4 gather loads per thread (halves per-SM L1tex wavefront queue vs 1 CTA/image).
// s values exchanged across the cluster via DSMEM; push j-range split by h.

#define B_IMGS  64
#define N_KP    128
#define HALF_KP 64
#define HW      65536   // 256*256
#define W_DIM   256
#define NBLK    128     // 2 CTAs per image

__device__ float g_pull[NBLK];
__device__ float g_push[NBLK];
__device__ unsigned int g_count;   // zero-init at load; reset in-kernel

__global__ __launch_bounds__(128, 1) __cluster_dims__(2, 1, 1)
void ae_cluster_kernel(const float* __restrict__ pred,
                       const float* __restrict__ target,
                       const int*   __restrict__ match,
                       float*       __restrict__ out) {
    const int blk = blockIdx.x;
    const int b   = blk >> 1;   // image
    const int r   = blk & 1;    // cluster rank (x-major)
    const int n   = threadIdx.x;
    const int k   = n >> 1;     // local keypoint 0..63
    const int h   = n & 1;      // channel half: channels {2h, 2h+1}
    const int gkp = r * HALF_KP + k;  // global keypoint index

    __shared__ float s_me[N_KP];   // all 128 s values (own half + peer half)
    __shared__ float s_red[8];
    __shared__ int   s_last;

    // match[b, gkp, {tl,br}, {y,x}] — both threads of a pair load the same int4
    const int4 m = __ldg(reinterpret_cast<const int4*>(match) + b * N_KP + gkp);
    const int tl_off = m.x * W_DIM + m.y;
    const int br_off = m.z * W_DIM + m.w;

    const float* __restrict__ p = pred   + ((size_t)b * 4 + 2 * h) * HW;
    const float* __restrict__ t = target + ((size_t)b * 4 + 2 * h) * HW;

    const float tl0 = __ldg(p + tl_off);
    const float tl1 = __ldg(p + HW + tl_off);
    const float br0 = __ldg(t + br_off);
    const float br1 = __ldg(t + HW + br_off);

    const float d0 = tl0 - br0, d1 = tl1 - br1;
    float pull = 0.5f * (d0 * d0 + d1 * d1);           // partial (2 channels)
    const float sp = 0.5f * ((tl0 + br0) + (tl1 + br1));

    // full s for this kp: combine the two channel-halves (adjacent lanes)
    const float s_full = sp + __shfl_xor_sync(0xFFFFFFFFu, sp, 1);

    // publish s: h==0 writes own smem slot, h==1 writes the peer CTA's slot
    cg::cluster_group cluster = cg::this_cluster();
    float* peer_me = cluster.map_shared_rank(s_me, r ^ 1);
    if (h == 0) s_me[gkp]   = s_full;
    else        peer_me[gkp] = s_full;
    cluster.sync();   // all 128 slots valid in both CTAs

    // push: thread covers j in [h*64, h*64+64)
    float p0 = 0.f, p1 = 0.f, p2 = 0.f, p3 = 0.f;
    const float4* __restrict__ s4 =
        reinterpret_cast<const float4*>(s_me + h * HALF_KP);
    #pragma unroll
    for (int j = 0; j < HALF_KP / 4; ++j) {
        const float4 v = s4[j];
        p0 += fmaxf(0.f, 1.f - fabsf(s_full - v.x));
        p1 += fmaxf(0.f, 1.f - fabsf(s_full - v.y));
        p2 += fmaxf(0.f, 1.f - fabsf(s_full - v.z));
        p3 += fmaxf(0.f, 1.f - fabsf(s_full - v.w));
    }
    float push = (p0 + p1) + (p2 + p3);
    if (h == r) push -= 1.0f;   // remove the j==gkp self term (==1)

    // block reduction (pull partials are per-(kp,2ch); push per-(kp,j-half))
    #pragma unroll
    for (int off = 16; off > 0; off >>= 1) {
        pull += __shfl_down_sync(0xFFFFFFFFu, pull, off);
        push += __shfl_down_sync(0xFFFFFFFFu, push, off);
    }
    const int warp = n >> 5;
    const int lane = n & 31;
    if (lane == 0) {
        s_red[warp]     = pull;
        s_red[4 + warp] = push;
    }
    __syncthreads();

    if (n == 0) {
        const float pu = s_red[0] + s_red[1] + s_red[2] + s_red[3];
        const float ph = s_red[4] + s_red[5] + s_red[6] + s_red[7];
        __stcg(&g_pull[blk], pu * (1.0f / (float)N_KP));
        __stcg(&g_push[blk], ph * (1.0f / (float)(N_KP * (N_KP - 1))));
        __threadfence();
        const unsigned int old = atomicAdd(&g_count, 1u);
        s_last = (old == (unsigned)(NBLK - 1)) ? 1 : 0;
    }
    __syncthreads();

    // last block: deterministic final reduction over 128 partials
    if (s_last && warp == 0) {
        __threadfence();  // acquire: order reads after the arrival atomics
        float pu = __ldcg(&g_pull[lane])      + __ldcg(&g_pull[lane + 32]) +
                   __ldcg(&g_pull[lane + 64]) + __ldcg(&g_pull[lane + 96]);
        float ph = __ldcg(&g_push[lane])      + __ldcg(&g_push[lane + 32]) +
                   __ldcg(&g_push[lane + 64]) + __ldcg(&g_push[lane + 96]);
        #pragma unroll
        for (int off = 16; off > 0; off >>= 1) {
            pu += __shfl_down_sync(0xFFFFFFFFu, pu, off);
            ph += __shfl_down_sync(0xFFFFFFFFu, ph, off);
        }
        if (lane == 0) {
            out[0] = 0.25f * pu;
            out[1] = 0.25f * ph;
            g_count = 0;   // reset for next graph replay
        }
    }
}

extern "C" void kernel_launch(void* const* d_in, const int* in_sizes, int n_in,
                              void* d_out, int out_size) {
    const float* pred   = (const float*)d_in[0];
    const float* target = (const float*)d_in[1];
    const int*   match  = (const int*)d_in[2];
    float* out = (float*)d_out;

    ae_cluster_kernel<<<NBLK, 128>>>(pred, target, match, out);
}

// round 5
// speedup vs baseline: 1.1245x; 1.0924x over previous
#include <cuda_runtime.h>

// AELoss: pred/target (64,4,256,256) fp32, match (64,128,2,2) int32.
// out[0] = 0.25 * sum_b pull_b, out[1] = 0.25 * sum_b push_b
//
// pull_b = sum_{n,c} (tl-br)^2 / 2 / N        (since tl-me = (tl-br)/2)
// push_b = sum_{i!=j} relu(1 - |s_i - s_j|) / (N*(N-1)),  s_i = sum_c (tl+br)/2
//
// Tail-free: each CTA RED-atomicAdds its scaled partials straight into out[],
// which is zeroed by a cudaMemsetAsync graph node before the kernel.

#define B_IMGS 64
#define N_KP   128
#define C_CH   4
#define HW     65536   // 256*256
#define W_DIM  256

__global__ __launch_bounds__(N_KP, 1)
void ae_kernel(const float* __restrict__ pred,
               const float* __restrict__ target,
               const int*   __restrict__ match,
               float*       __restrict__ out) {
    const int b = blockIdx.x;
    const int n = threadIdx.x;

    __shared__ float s_me[N_KP];
    __shared__ float s_red[8];   // 4 warps x 2 values

    // match[b, n, {tl,br}, {y,x}] -- one int4 per (b,n)
    const int4 m = __ldg(reinterpret_cast<const int4*>(match) + b * N_KP + n);
    const int tl_off = m.x * W_DIM + m.y;
    const int br_off = m.z * W_DIM + m.w;

    const float* __restrict__ p = pred   + (size_t)b * C_CH * HW;
    const float* __restrict__ t = target + (size_t)b * C_CH * HW;

    float pull = 0.0f;
    float s    = 0.0f;
    #pragma unroll
    for (int c = 0; c < C_CH; ++c) {
        const float tl = __ldg(p + c * HW + tl_off);
        const float br = __ldg(t + c * HW + br_off);
        const float d = tl - br;
        pull += 0.5f * d * d;
        s    += 0.5f * (tl + br);
    }
    s_me[n] = s;
    __syncthreads();

    // push over all j (smem broadcast, vectorized); subtract the j==n term (==1)
    float push = -1.0f;
    const float4* __restrict__ s4 = reinterpret_cast<const float4*>(s_me);
    #pragma unroll
    for (int j = 0; j < N_KP / 4; ++j) {
        const float4 v = s4[j];
        push += fmaxf(0.0f, 1.0f - fabsf(s - v.x));
        push += fmaxf(0.0f, 1.0f - fabsf(s - v.y));
        push += fmaxf(0.0f, 1.0f - fabsf(s - v.z));
        push += fmaxf(0.0f, 1.0f - fabsf(s - v.w));
    }

    // block reduction of (pull, push)
    #pragma unroll
    for (int off = 16; off > 0; off >>= 1) {
        pull += __shfl_down_sync(0xFFFFFFFFu, pull, off);
        push += __shfl_down_sync(0xFFFFFFFFu, push, off);
    }
    const int warp = n >> 5;
    const int lane = n & 31;
    if (lane == 0) {
        s_red[warp]     = pull;
        s_red[4 + warp] = push;
    }
    __syncthreads();

    // fire-and-forget global reduction: 2 RED.ADD per CTA, no tail chain
    if (n == 0) {
        const float pu = s_red[0] + s_red[1] + s_red[2] + s_red[3];
        const float ph = s_red[4] + s_red[5] + s_red[6] + s_red[7];
        atomicAdd(&out[0], pu * (0.25f / (float)N_KP));
        atomicAdd(&out[1], ph * (0.25f / (float)(N_KP * (N_KP - 1))));
    }
}

extern "C" void kernel_launch(void* const* d_in, const int* in_sizes, int n_in,
                              void* d_out, int out_size) {
    const float* pred   = (const float*)d_in[0];
    const float* target = (const float*)d_in[1];
    const int*   match  = (const int*)d_in[2];
    float* out = (float*)d_out;

    cudaMemsetAsync(out, 0, 2 * sizeof(float));
    ae_kernel<<<B_IMGS, N_KP>>>(pred, target, match, out);
}